// round 2
// baseline (speedup 1.0000x reference)
#include <cuda_runtime.h>
#include <math.h>

#define NN 1000
#define FF 128
#define TT 4
#define PP 10
#define DD 13
#define EE 20000
#define EAD 16
#define HH 128
#define KK 64
#define NDIM 13000        // N*D
#define IEDGE 169
#define INODE 91
#define WNS 172           // padded Wn row stride (mult of 4)
#define WCPAD 68          // padded Wc smem row stride (17 float4 groups, odd -> no bank conflicts)
#define WPPAD 132         // padded Wp smem row stride (33 float4 groups, odd)

// zero-fill region boundaries, in float4 units (total = 169e6/4 = 42,250,000)
#define TOT4 42250000
#define Z1    2048000     // k_node_prep:  [0, Z1)
#define Z2    8448000     // k_edge_agg:   [Z1, Z2)
#define Z3   23808000     // k_edge_msg:   [Z2, Z3)
#define Z4   29568000     // k_node_out:   [Z3, Z4)
                          // k_edge_blocks:[Z4, TOT4)

// ---------------- scratch (device globals; no runtime allocation) ----------------
__device__ __align__(16) float g_m[NN*FF];
__device__ float g_base[NN*FF];
__device__ float g_agg[NN*FF];
__device__ float g_r1[NN*HH];
__device__ float g_r2[NN*HH];
__device__ float g_q1[NN*KK];
__device__ float g_q2[NN*KK];
__device__ __align__(16) float g_Wn[TT*FF*WNS];     // [t][f][xy(pad 172)] = W_node @ cob_node
__device__ __align__(16) float g_WcT[PP*IEDGE*KK];  // [p][xy][k]          = (W_edge @ cob_edge)^T
__device__ __align__(16) float g_h[EE*2*KK];        // per-edge [h_ij(64) | h_ji(64)]
__device__ __align__(16) float g_blk[(size_t)EE*IEDGE];   // symmetrized 13x13 edge blocks
__device__ float g_nblk[NN*IEDGE];                  // node diagonal blocks
__device__ int   g_cnt[PP];
__device__ int   g_off[PP+1];
__device__ int   g_cur[PP];
__device__ int   g_bucket[EE];
__device__ int   g_rowcnt[NN];
__device__ int   g_rowoff[NN+1];
__device__ int   g_rowcur[NN];
__device__ int   g_rentry[2*EE];                    // e*2 | transposed-flag

__device__ __forceinline__ void zero_region(float4* out4, int lo, int hi, int gt, int nth) {
    float4 z = make_float4(0.f, 0.f, 0.f, 0.f);
    for (int i = lo + gt; i < hi; i += nth) out4[i] = z;
}

// ---------------- precompute fused change-of-basis weights ----------------
__global__ void k_pre_node(const float* __restrict__ Wnode, const float* __restrict__ cobn) {
    int idx = blockIdx.x*blockDim.x + threadIdx.x;
    if (idx < TT*FF*3) {  // zero pad columns so later float4 reads are benign
        g_Wn[(idx/3)*WNS + IEDGE + (idx%3)] = 0.f;
    }
    if (idx >= TT*FF*IEDGE) return;
    int xy  = idx % IEDGE;
    int rem = idx / IEDGE;
    int f = rem % FF, t = rem / FF;
    const float* w = Wnode + (t*FF + f)*INODE;
    const float* c = cobn + t*INODE*IEDGE + xy;
    float acc = 0.f;
    #pragma unroll 7
    for (int i = 0; i < INODE; i++) acc += w[i]*c[i*IEDGE];
    g_Wn[(t*FF + f)*WNS + xy] = acc;
}

__global__ void k_pre_edge(const float* __restrict__ Wedge, const float* __restrict__ cobe) {
    int idx = blockIdx.x*blockDim.x + threadIdx.x;
    if (idx >= PP*KK*IEDGE) return;
    int xy  = idx % IEDGE;
    int rem = idx / IEDGE;
    int k = rem % KK, p = rem / KK;
    const float* w = Wedge + (p*KK + k)*IEDGE;
    const float* c = cobe + (size_t)p*IEDGE*IEDGE + xy;
    float acc = 0.f;
    #pragma unroll 13
    for (int i = 0; i < IEDGE; i++) acc += w[i]*c[i*IEDGE];
    g_WcT[(p*IEDGE + xy)*KK + k] = acc;   // transposed store: [xy][k]
}

// ---------------- node prep: m = nf@Wmsg, base = nf + na@Wattr, zero agg+counters ----------------
__global__ void k_node_prep(const float* __restrict__ nf, const float* __restrict__ na,
                            const float* __restrict__ Wmsg, const float* __restrict__ Wattr,
                            float4* __restrict__ out4) {
    int n = blockIdx.x;
    int f = threadIdx.x;   // 128
    int gt = n*FF + f;
    zero_region(out4, 0, Z1, gt, NN*FF);
    __shared__ float row[FF];
    row[f] = nf[n*FF + f];
    if (gt < NN) { g_rowcnt[gt] = 0; g_rowcur[gt] = 0; }
    if (gt < PP) { g_cnt[gt] = 0; g_cur[gt] = 0; }
    __syncthreads();
    float acc = 0.f;
    #pragma unroll 8
    for (int g = 0; g < FF; g++) acc += row[g] * Wmsg[g*FF + f];
    g_m[n*FF + f] = acc;
    float b = row[f];
    #pragma unroll
    for (int t = 0; t < TT; t++) b += na[n*TT + t] * Wattr[t*FF + f];
    g_base[n*FF + f] = b;
    g_agg[n*FF + f] = 0.f;
}

// ---------------- symmetric edge aggregation (+ type & row histograms) ----------------
__global__ void k_edge_agg(const int* __restrict__ ei, const int* __restrict__ et,
                           float4* __restrict__ out4) {
    int idx = blockIdx.x*blockDim.x + threadIdx.x;   // EE*32 threads
    zero_region(out4, Z1, Z2, idx, EE*32);
    if (idx >= EE*32) return;
    int e = idx >> 5, u = idx & 31;
    int s = ei[e], d = ei[EE + e];
    float4 ms = *(const float4*)&g_m[s*FF + u*4];
    float4 md = *(const float4*)&g_m[d*FF + u*4];
    atomicAdd(&g_agg[d*FF + u*4 + 0], ms.x);
    atomicAdd(&g_agg[d*FF + u*4 + 1], ms.y);
    atomicAdd(&g_agg[d*FF + u*4 + 2], ms.z);
    atomicAdd(&g_agg[d*FF + u*4 + 3], ms.w);
    atomicAdd(&g_agg[s*FF + u*4 + 0], md.x);
    atomicAdd(&g_agg[s*FF + u*4 + 1], md.y);
    atomicAdd(&g_agg[s*FF + u*4 + 2], md.z);
    atomicAdd(&g_agg[s*FF + u*4 + 3], md.w);
    if (u == 0) {
        atomicAdd(&g_cnt[et[e]], 1);
        atomicAdd(&g_rowcnt[s], 1);
        atomicAdd(&g_rowcnt[d], 1);
    }
}

// ---------------- scans: 1000-row exclusive scan + 10-type serial scan ----------------
__global__ void k_scan() {
    __shared__ int sm[1024];
    int tid = threadIdx.x;
    int v = (tid < NN) ? g_rowcnt[tid] : 0;
    sm[tid] = v;
    __syncthreads();
    #pragma unroll
    for (int off = 1; off < 1024; off <<= 1) {
        int t = (tid >= off) ? sm[tid - off] : 0;
        __syncthreads();
        sm[tid] += t;
        __syncthreads();
    }
    if (tid < NN) g_rowoff[tid] = sm[tid] - v;
    if (tid == NN - 1) g_rowoff[NN] = sm[tid];
    if (tid == 0) {
        int acc = 0;
        for (int p = 0; p < PP; p++) { g_off[p] = acc; acc += g_cnt[p]; }
        g_off[PP] = acc;
    }
}

__global__ void k_bucket(const int* __restrict__ ei, const int* __restrict__ et) {
    int e = blockIdx.x*blockDim.x + threadIdx.x;
    if (e >= EE) return;
    int p = et[e];
    g_bucket[g_off[p] + atomicAdd(&g_cur[p], 1)] = e;
    int s = ei[e], d = ei[EE + e];
    g_rentry[g_rowoff[s] + atomicAdd(&g_rowcur[s], 1)] = e*2;       // block at (s, d)
    g_rentry[g_rowoff[d] + atomicAdd(&g_rowcur[d], 1)] = e*2 + 1;   // block^T at (d, s)
}

// ---------------- per-node outputs: r1,r2,q1,q2 and diagonal blocks ----------------
__global__ void k_node_out(const float* __restrict__ Wem, const float* __restrict__ Wproj,
                           const int* __restrict__ ntype, float4* __restrict__ out4) {
    int n   = blockIdx.x;
    int tid = threadIdx.x;   // 192
    zero_region(out4, Z3, Z4, n*192 + tid, NN*192);
    __shared__ float nh[FF];
    if (tid < FF) nh[tid] = g_base[n*FF + tid] + g_agg[n*FF + tid] * 0.05f;
    __syncthreads();
    int t = ntype[n];
    const int NTASK = 96 + 43;   // 32 r1 + 32 r2 + 16 q1 + 16 q2 + 43 nb (float4 tasks)
    for (int o = tid; o < NTASK; o += blockDim.x) {
        const float4* w4; int stride4, kind, c0;
        if (o < 32)      { c0 = o*4;        w4 = (const float4*)(Wem + c0);               stride4 = HH/4;  kind = 0; }
        else if (o < 64) { c0 = (o-32)*4;   w4 = (const float4*)(Wem + FF*HH + c0);       stride4 = HH/4;  kind = 1; }
        else if (o < 80) { c0 = (o-64)*4;   w4 = (const float4*)(Wproj + FF*KK + c0);     stride4 = KK/4;  kind = 2; }
        else if (o < 96) { c0 = (o-80)*4;   w4 = (const float4*)(Wproj + 2*FF*KK + c0);   stride4 = KK/4;  kind = 3; }
        else             { c0 = (o-96)*4;   w4 = (const float4*)(g_Wn + t*FF*WNS + c0);   stride4 = WNS/4; kind = 4; }
        float4 acc = make_float4(0.f, 0.f, 0.f, 0.f);
        #pragma unroll 4
        for (int g = 0; g < FF; g++) {
            float4 w = w4[g*stride4];
            float h = nh[g];
            acc.x += h*w.x; acc.y += h*w.y; acc.z += h*w.z; acc.w += h*w.w;
        }
        if (kind == 0)      *(float4*)&g_r1[n*HH + c0] = acc;
        else if (kind == 1) *(float4*)&g_r2[n*HH + c0] = acc;
        else if (kind == 2) *(float4*)&g_q1[n*KK + c0] = acc;
        else if (kind == 3) *(float4*)&g_q2[n*KK + c0] = acc;
        else {
            float v[4] = {acc.x, acc.y, acc.z, acc.w};
            #pragma unroll
            for (int j = 0; j < 4; j++) {
                int xy = c0 + j;
                if (xy < IEDGE) g_nblk[n*IEDGE + xy] = v[j];
            }
        }
    }
}

// ---------------- per-edge: edge_msg -> u -> h_ij/h_ji ----------------
__global__ void k_edge_msg(const float* __restrict__ ef, const float* __restrict__ ea,
                           const float* __restrict__ Wem, const float* __restrict__ Wproj,
                           const int* __restrict__ ei, float4* __restrict__ out4) {
    __shared__ __align__(16) float wp[KK*WPPAD];   // [c(64)][g(128) pad 132] = W_proj rows 0..127 transposed
    __shared__ __align__(16) float msg[HH];
    __shared__ float eatt[2*EAD];
    int tid = threadIdx.x;   // 128
    zero_region(out4, Z2, Z3, blockIdx.x*blockDim.x + tid, gridDim.x*blockDim.x);
    float emreg[32];         // column tid of W_em rows 256..287 (edge_feats/attrs part)
    #pragma unroll
    for (int j = 0; j < 32; j++) emreg[j] = Wem[(2*FF + j)*HH + tid];
    for (int i = tid; i < FF*KK; i += blockDim.x) {
        int r = i >> 6, c = i & 63;       // coalesced read of Wproj, transpose into smem
        wp[c*WPPAD + r] = Wproj[i];
    }
    __syncthreads();
    for (int e = blockIdx.x; e < EE; e += gridDim.x) {
        int s = ei[e], d = ei[EE + e];
        if (tid < 2*EAD) eatt[tid] = (tid < EAD) ? ef[e*EAD + tid] : ea[e*EAD + (tid - EAD)];
        __syncthreads();
        float fe = 0.f;
        #pragma unroll
        for (int j = 0; j < 32; j++) fe += eatt[j]*emreg[j];
        msg[tid] = tanhf(g_r1[s*HH + tid] + g_r2[d*HH + tid] + fe);
        __syncthreads();
        if (tid < KK) {
            const float4* wr = (const float4*)&wp[tid*WPPAD];
            const float4* mg = (const float4*)msg;
            float u = 0.f;
            #pragma unroll 8
            for (int g = 0; g < HH/4; g++) {
                float4 a = wr[g], b = mg[g];
                u += a.x*b.x + a.y*b.y + a.z*b.z + a.w*b.w;
            }
            g_h[e*2*KK + tid]      = u + g_q1[s*KK + tid] + g_q2[d*KK + tid];
            g_h[e*2*KK + KK + tid] = u + g_q1[d*KK + tid] + g_q2[s*KK + tid];
        }
        __syncthreads();
    }
}

// ---------------- per-edge 13x13 symmetrized blocks -> g_blk (dense, no atomics) ----------------
__global__ void k_edge_blocks(float4* __restrict__ out4) {
    int p   = blockIdx.y;
    int tid = threadIdx.x;   // 192
    {
        int bid = blockIdx.y*gridDim.x + blockIdx.x;
        zero_region(out4, Z4, TOT4, bid*blockDim.x + tid, gridDim.x*gridDim.y*blockDim.x);
    }
    __shared__ __align__(16) float wc[IEDGE*WCPAD];   // [xy][k pad 68]
    __shared__ __align__(16) float hsm[4*2*KK];       // 4 edges x [h_ij|h_ji]
    int beg = g_off[p], end = g_off[p+1];
    int cnt = end - beg;
    int per = (cnt + gridDim.x - 1) / gridDim.x;
    int lo  = beg + blockIdx.x * per;
    int hi  = min(lo + per, end);
    if (lo >= hi) return;   // uniform per block
    const float* srcw = g_WcT + p*IEDGE*KK;
    for (int i = tid; i < IEDGE*(KK/4); i += blockDim.x) {
        int xy = i >> 4, kk = i & 15;
        ((float4*)(wc + xy*WCPAD))[kk] = ((const float4*)(srcw + xy*KK))[kk];
    }
    __syncthreads();
    int x = 0, y = 0, xyt = 0;
    if (tid < IEDGE) { x = tid/DD; y = tid - x*DD; xyt = y*DD + x; }
    for (int base = lo; base < hi; base += 4) {
        int ne = min(4, hi - base);
        for (int i = tid; i < 4*2*KK; i += blockDim.x) {
            int el = i >> 7, off = i & 127;
            float v = 0.f;
            if (el < ne) v = g_h[(size_t)g_bucket[base + el]*2*KK + off];
            hsm[i] = v;
        }
        __syncthreads();
        if (tid < IEDGE) {
            const float4* wf = (const float4*)(wc + tid*WCPAD);
            const float4* wt = (const float4*)(wc + xyt*WCPAD);
            const float4* h4 = (const float4*)hsm;
            float a[4] = {0.f,0.f,0.f,0.f}, b[4] = {0.f,0.f,0.f,0.f};
            #pragma unroll
            for (int kk = 0; kk < KK/4; kk++) {
                float4 f = wf[kk], t = wt[kk];
                #pragma unroll
                for (int el = 0; el < 4; el++) {
                    float4 hf = h4[el*32 + kk];        // h_ij
                    float4 hb = h4[el*32 + 16 + kk];   // h_ji
                    a[el] += hf.x*f.x + hf.y*f.y + hf.z*f.z + hf.w*f.w;
                    b[el] += hb.x*t.x + hb.y*t.y + hb.z*t.z + hb.w*t.w;
                }
            }
            #pragma unroll
            for (int el = 0; el < 4; el++) {
                if (el < ne) {
                    int e = g_bucket[base + el];       // broadcast load
                    g_blk[(size_t)e*IEDGE + tid] = 0.5f*(a[el] + b[el]);
                }
            }
        }
        __syncthreads();
    }
}

// ---------------- assemble output: CTA i owns row-strip i; plain RMW, race-free ----------------
__global__ void k_patch(const int* __restrict__ ei, float* __restrict__ M) {
    int i   = blockIdx.x;
    int tid = threadIdx.x;   // 192
    if (tid >= IEDGE) return;
    int x = tid/DD, y = tid - (tid/DD)*DD;
    size_t rowbase = (size_t)(i*DD + x)*NDIM + y;
    // node diagonal block
    M[rowbase + (size_t)i*DD] += g_nblk[i*IEDGE + tid];
    int lo = g_rowoff[i], hi = g_rowoff[i+1];
    for (int q = lo; q < hi; q++) {
        int v = g_rentry[q];            // broadcast
        int e = v >> 1, f = v & 1;
        int j = f ? ei[e] : ei[EE + e]; // column block
        float val = g_blk[(size_t)e*IEDGE + (f ? y*DD + x : tid)];
        M[rowbase + (size_t)j*DD] += val;
    }
}

// ---------------- launcher ----------------
extern "C" void kernel_launch(void* const* d_in, const int* in_sizes, int n_in,
                              void* d_out, int out_size) {
    const float* nf    = (const float*)d_in[0];
    const float* na    = (const float*)d_in[1];
    const float* ef    = (const float*)d_in[2];
    const float* ea    = (const float*)d_in[3];
    const int*   ei    = (const int*)d_in[4];
    const int*   ntype = (const int*)d_in[5];
    const int*   etype = (const int*)d_in[6];
    const float* Wmsg  = (const float*)d_in[7];
    const float* Wattr = (const float*)d_in[8];
    const float* Wem   = (const float*)d_in[9];
    const float* Wproj = (const float*)d_in[10];
    const float* Wnode = (const float*)d_in[11];
    const float* Wedge = (const float*)d_in[12];
    const float* cobn  = (const float*)d_in[13];
    const float* cobe  = (const float*)d_in[14];
    float* M = (float*)d_out;
    float4* M4 = (float4*)d_out;

    k_pre_node<<<(TT*FF*IEDGE + 255)/256, 256>>>(Wnode, cobn);
    k_pre_edge<<<(PP*KK*IEDGE + 255)/256, 256>>>(Wedge, cobe);
    k_node_prep<<<NN, FF>>>(nf, na, Wmsg, Wattr, M4);
    k_edge_agg<<<(EE*32 + 255)/256, 256>>>(ei, etype, M4);
    k_scan<<<1, 1024>>>();
    k_bucket<<<(EE + 255)/256, 256>>>(ei, etype);
    k_node_out<<<NN, 192>>>(Wem, Wproj, ntype, M4);
    k_edge_msg<<<2000, 128>>>(ef, ea, Wem, Wproj, ei, M4);
    k_edge_blocks<<<dim3(64, PP), 192>>>(M4);
    k_patch<<<NN, 192>>>(ei, M);
}

// round 3
// speedup vs baseline: 1.0610x; 1.0610x over previous
#include <cuda_runtime.h>
#include <math.h>

#define NN 1000
#define FF 128
#define TT 4
#define PP 10
#define DD 13
#define EE 20000
#define EAD 16
#define HH 128
#define KK 64
#define NDIM 13000        // N*D
#define IEDGE 169
#define INODE 91
#define WNS 172           // padded Wn row stride (mult of 4)
#define WCPAD 68          // padded Wc smem row stride (17 float4 groups, odd -> no bank conflicts)
#define WPPAD 132         // padded Wp smem row stride (33 float4 groups, odd)
#define STRIP4 42250      // floats4 per node row-strip: 13*13000/4

// ---------------- scratch (device globals; no runtime allocation) ----------------
__device__ __align__(16) float g_m[NN*FF];
__device__ float g_base[NN*FF];
__device__ float g_nh[NN*FF];
__device__ float g_r1[NN*HH];
__device__ float g_r2[NN*HH];
__device__ float g_q1[NN*KK];
__device__ float g_q2[NN*KK];
__device__ __align__(16) float g_Wn[TT*FF*WNS];     // [t][f][xy(pad 172)] = W_node @ cob_node
__device__ __align__(16) float g_WcT[PP*IEDGE*KK];  // [p][xy][k]          = (W_edge @ cob_edge)^T
__device__ __align__(16) float g_h[EE*2*KK];        // per-edge [h_ij(64) | h_ji(64)]
__device__ __align__(16) float g_blk[(size_t)EE*IEDGE];   // symmetrized blocks B
__device__ __align__(16) float g_blkT[(size_t)EE*IEDGE];  // B^T
__device__ float g_nblk[NN*IEDGE];                  // node diagonal blocks
__device__ int   g_cnt[PP];
__device__ int   g_off[PP+1];
__device__ int   g_cur[PP];
__device__ int   g_bucket[EE];
__device__ int   g_rowcnt[NN];
__device__ int   g_rowoff[NN+1];
__device__ int   g_rowcur[NN];
__device__ int   g_rentry[2*EE];                    // e*2 | flag (flag=1 -> transposed/row-dst)

// ---------------- precompute fused change-of-basis weights ----------------
__global__ void k_pre_node(const float* __restrict__ Wnode, const float* __restrict__ cobn) {
    int idx = blockIdx.x*blockDim.x + threadIdx.x;
    if (idx < TT*FF*3) {  // zero pad columns so later float4 reads are benign
        g_Wn[(idx/3)*WNS + IEDGE + (idx%3)] = 0.f;
    }
    if (idx >= TT*FF*IEDGE) return;
    int xy  = idx % IEDGE;
    int rem = idx / IEDGE;
    int f = rem % FF, t = rem / FF;
    const float* w = Wnode + (t*FF + f)*INODE;
    const float* c = cobn + t*INODE*IEDGE + xy;
    float acc = 0.f;
    #pragma unroll 7
    for (int i = 0; i < INODE; i++) acc += w[i]*c[i*IEDGE];
    g_Wn[(t*FF + f)*WNS + xy] = acc;
}

__global__ void k_pre_edge(const float* __restrict__ Wedge, const float* __restrict__ cobe) {
    int idx = blockIdx.x*blockDim.x + threadIdx.x;
    if (idx >= PP*KK*IEDGE) return;
    int xy  = idx % IEDGE;
    int rem = idx / IEDGE;
    int k = rem % KK, p = rem / KK;
    const float* w = Wedge + (p*KK + k)*IEDGE;
    const float* c = cobe + (size_t)p*IEDGE*IEDGE + xy;
    float acc = 0.f;
    #pragma unroll 13
    for (int i = 0; i < IEDGE; i++) acc += w[i]*c[i*IEDGE];
    g_WcT[(p*IEDGE + xy)*KK + k] = acc;   // transposed store: [xy][k]
}

// ---------------- node prep: m = nf@Wmsg, base = nf + na@Wattr, zero counters ----------------
__global__ void k_node_prep(const float* __restrict__ nf, const float* __restrict__ na,
                            const float* __restrict__ Wmsg, const float* __restrict__ Wattr) {
    int n = blockIdx.x;
    int f = threadIdx.x;   // 128
    int gt = n*FF + f;
    __shared__ float row[FF];
    row[f] = nf[gt];
    if (gt < NN) { g_rowcnt[gt] = 0; g_rowcur[gt] = 0; }
    if (gt < PP) { g_cnt[gt] = 0; g_cur[gt] = 0; }
    __syncthreads();
    float acc = 0.f;
    #pragma unroll 8
    for (int g = 0; g < FF; g++) acc += row[g] * Wmsg[g*FF + f];
    g_m[gt] = acc;
    float b = row[f];
    #pragma unroll
    for (int t = 0; t < TT; t++) b += na[n*TT + t] * Wattr[t*FF + f];
    g_base[gt] = b;
}

// ---------------- histograms ----------------
__global__ void k_hist(const int* __restrict__ ei, const int* __restrict__ et) {
    int e = blockIdx.x*blockDim.x + threadIdx.x;
    if (e >= EE) return;
    atomicAdd(&g_cnt[et[e]], 1);
    atomicAdd(&g_rowcnt[ei[e]], 1);
    atomicAdd(&g_rowcnt[ei[EE + e]], 1);
}

// ---------------- scans: 1000-row exclusive scan + 10-type serial scan ----------------
__global__ void k_scan() {
    __shared__ int sm[1024];
    int tid = threadIdx.x;
    int v = (tid < NN) ? g_rowcnt[tid] : 0;
    sm[tid] = v;
    __syncthreads();
    #pragma unroll
    for (int off = 1; off < 1024; off <<= 1) {
        int t = (tid >= off) ? sm[tid - off] : 0;
        __syncthreads();
        sm[tid] += t;
        __syncthreads();
    }
    if (tid < NN) g_rowoff[tid] = sm[tid] - v;
    if (tid == NN - 1) g_rowoff[NN] = sm[tid];
    if (tid == 0) {
        int acc = 0;
        for (int p = 0; p < PP; p++) { g_off[p] = acc; acc += g_cnt[p]; }
        g_off[PP] = acc;
    }
}

__global__ void k_bucket(const int* __restrict__ ei, const int* __restrict__ et) {
    int e = blockIdx.x*blockDim.x + threadIdx.x;
    if (e >= EE) return;
    int p = et[e];
    g_bucket[g_off[p] + atomicAdd(&g_cur[p], 1)] = e;
    int s = ei[e], d = ei[EE + e];
    g_rentry[g_rowoff[s] + atomicAdd(&g_rowcur[s], 1)] = e*2;       // block at (s, d)
    g_rentry[g_rowoff[d] + atomicAdd(&g_rowcur[d], 1)] = e*2 + 1;   // block^T at (d, s)
}

// ---------------- gather aggregation: nh = base + (sum_neigh m)/20 (no atomics) ----------------
__global__ void k_gather(const int* __restrict__ ei) {
    int n = blockIdx.x;
    int f = threadIdx.x;   // 128
    float acc = 0.f;
    int lo = g_rowoff[n], hi = g_rowoff[n+1];
    for (int q = lo; q < hi; q++) {
        int v = g_rentry[q];               // broadcast
        int e = v >> 1;
        int other = (v & 1) ? ei[e] : ei[EE + e];
        acc += g_m[other*FF + f];
    }
    g_nh[n*FF + f] = g_base[n*FF + f] + acc * 0.05f;
}

// ---------------- per-node outputs: r1,r2,q1,q2 and diagonal blocks ----------------
__global__ void k_node_out(const float* __restrict__ Wem, const float* __restrict__ Wproj,
                           const int* __restrict__ ntype) {
    int n   = blockIdx.x;
    int tid = threadIdx.x;   // 160
    __shared__ float nh[FF];
    if (tid < FF) nh[tid] = g_nh[n*FF + tid];
    __syncthreads();
    int t = ntype[n];
    const int NTASK = 96 + 43;   // 32 r1 + 32 r2 + 16 q1 + 16 q2 + 43 nb (float4 tasks)
    for (int o = tid; o < NTASK; o += blockDim.x) {
        const float4* w4; int stride4, kind, c0;
        if (o < 32)      { c0 = o*4;        w4 = (const float4*)(Wem + c0);               stride4 = HH/4;  kind = 0; }
        else if (o < 64) { c0 = (o-32)*4;   w4 = (const float4*)(Wem + FF*HH + c0);       stride4 = HH/4;  kind = 1; }
        else if (o < 80) { c0 = (o-64)*4;   w4 = (const float4*)(Wproj + FF*KK + c0);     stride4 = KK/4;  kind = 2; }
        else if (o < 96) { c0 = (o-80)*4;   w4 = (const float4*)(Wproj + 2*FF*KK + c0);   stride4 = KK/4;  kind = 3; }
        else             { c0 = (o-96)*4;   w4 = (const float4*)(g_Wn + t*FF*WNS + c0);   stride4 = WNS/4; kind = 4; }
        float4 acc = make_float4(0.f, 0.f, 0.f, 0.f);
        #pragma unroll 4
        for (int g = 0; g < FF; g++) {
            float4 w = w4[g*stride4];
            float h = nh[g];
            acc.x += h*w.x; acc.y += h*w.y; acc.z += h*w.z; acc.w += h*w.w;
        }
        if (kind == 0)      *(float4*)&g_r1[n*HH + c0] = acc;
        else if (kind == 1) *(float4*)&g_r2[n*HH + c0] = acc;
        else if (kind == 2) *(float4*)&g_q1[n*KK + c0] = acc;
        else if (kind == 3) *(float4*)&g_q2[n*KK + c0] = acc;
        else {
            float v[4] = {acc.x, acc.y, acc.z, acc.w};
            #pragma unroll
            for (int j = 0; j < 4; j++) {
                int xy = c0 + j;
                if (xy < IEDGE) g_nblk[n*IEDGE + xy] = v[j];
            }
        }
    }
}

// ---------------- per-edge: edge_msg -> u -> h_ij/h_ji (4 edges per iteration) ----------------
__global__ void __launch_bounds__(128) k_edge_msg(const float* __restrict__ ef, const float* __restrict__ ea,
                                                  const float* __restrict__ Wem, const float* __restrict__ Wproj,
                                                  const int* __restrict__ ei) {
    __shared__ __align__(16) float wp[KK*WPPAD];   // [c(64)][g(128) pad 132] W_proj rows 0..127 transposed
    __shared__ __align__(16) float msg[4][HH];
    __shared__ float eatt[4][32];
    __shared__ int sd[8];
    int tid = threadIdx.x;   // 128
    float emreg[32];         // column tid of W_em rows 256..287 (edge feats/attrs part)
    #pragma unroll
    for (int j = 0; j < 32; j++) emreg[j] = Wem[(2*FF + j)*HH + tid];
    for (int i = tid; i < FF*KK; i += 128) {
        int r = i >> 6, c = i & 63;       // coalesced read of Wproj, transpose into smem
        wp[c*WPPAD + r] = Wproj[i];
    }
    __syncthreads();
    for (int grp = blockIdx.x; grp < EE/4; grp += gridDim.x) {
        int e0 = grp*4;
        {
            int el = tid >> 5, j = tid & 31;
            eatt[el][j] = (j < EAD) ? ef[(e0+el)*EAD + j] : ea[(e0+el)*EAD + (j - EAD)];
        }
        if (tid < 8) sd[tid] = ei[(tid & 1)*EE + e0 + (tid >> 1)];
        __syncthreads();
        #pragma unroll
        for (int el = 0; el < 4; el++) {
            float fe = 0.f;
            #pragma unroll
            for (int j = 0; j < 32; j++) fe += eatt[el][j]*emreg[j];
            float pre = g_r1[sd[2*el]*HH + tid] + g_r2[sd[2*el+1]*HH + tid] + fe;
            float ex = __expf(2.f*pre);                  // tanh = 1 - 2/(e^{2x}+1)
            msg[el][tid] = 1.f - __fdividef(2.f, ex + 1.f);
        }
        __syncthreads();
        int c = tid & 63, hh = tid >> 6;
        const float4* wr = (const float4*)&wp[c*WPPAD];
        const float4* m0 = (const float4*)msg[2*hh];
        const float4* m1 = (const float4*)msg[2*hh + 1];
        float u0 = 0.f, u1 = 0.f;
        #pragma unroll 8
        for (int g = 0; g < HH/4; g++) {
            float4 w = wr[g]; float4 a = m0[g]; float4 b = m1[g];
            u0 += w.x*a.x + w.y*a.y + w.z*a.z + w.w*a.w;
            u1 += w.x*b.x + w.y*b.y + w.z*b.z + w.w*b.w;
        }
        #pragma unroll
        for (int q = 0; q < 2; q++) {
            int el = 2*hh + q;
            float u = q ? u1 : u0;
            int e = e0 + el, s = sd[2*el], d = sd[2*el + 1];
            g_h[e*2*KK + c]      = u + g_q1[s*KK + c] + g_q2[d*KK + c];
            g_h[e*2*KK + KK + c] = u + g_q1[d*KK + c] + g_q2[s*KK + c];
        }
        __syncthreads();
    }
}

// ---------------- per-edge 13x13 symmetrized blocks -> g_blk + g_blkT (dense, no atomics) ----------------
__global__ void k_edge_blocks() {
    int p   = blockIdx.y;
    int tid = threadIdx.x;   // 192
    __shared__ __align__(16) float wc[IEDGE*WCPAD];   // [xy][k pad 68]
    __shared__ __align__(16) float hsm[4*2*KK];       // 4 edges x [h_ij|h_ji]
    __shared__ float tr[4][IEDGE + 3];                // transpose staging
    int beg = g_off[p], end = g_off[p+1];
    int cnt = end - beg;
    int per = (cnt + gridDim.x - 1) / gridDim.x;
    int lo  = beg + blockIdx.x * per;
    int hi  = min(lo + per, end);
    if (lo >= hi) return;   // uniform per block
    const float* srcw = g_WcT + p*IEDGE*KK;
    for (int i = tid; i < IEDGE*(KK/4); i += blockDim.x) {
        int xy = i >> 4, kk = i & 15;
        ((float4*)(wc + xy*WCPAD))[kk] = ((const float4*)(srcw + xy*KK))[kk];
    }
    __syncthreads();
    int x = 0, y = 0, xyt = 0;
    if (tid < IEDGE) { x = tid/DD; y = tid - x*DD; xyt = y*DD + x; }
    for (int base = lo; base < hi; base += 4) {
        int ne = min(4, hi - base);
        for (int i = tid; i < 4*2*KK; i += blockDim.x) {
            int el = i >> 7, off = i & 127;
            float v = 0.f;
            if (el < ne) v = g_h[(size_t)g_bucket[base + el]*2*KK + off];
            hsm[i] = v;
        }
        __syncthreads();
        if (tid < IEDGE) {
            const float4* wf = (const float4*)(wc + tid*WCPAD);
            const float4* wt = (const float4*)(wc + xyt*WCPAD);
            const float4* h4 = (const float4*)hsm;
            float a[4] = {0.f,0.f,0.f,0.f}, b[4] = {0.f,0.f,0.f,0.f};
            #pragma unroll
            for (int kk = 0; kk < KK/4; kk++) {
                float4 f = wf[kk], t = wt[kk];
                #pragma unroll
                for (int el = 0; el < 4; el++) {
                    float4 hf = h4[el*32 + kk];        // h_ij
                    float4 hb = h4[el*32 + 16 + kk];   // h_ji
                    a[el] += hf.x*f.x + hf.y*f.y + hf.z*f.z + hf.w*f.w;
                    b[el] += hb.x*t.x + hb.y*t.y + hb.z*t.z + hb.w*t.w;
                }
            }
            #pragma unroll
            for (int el = 0; el < 4; el++) {
                if (el < ne) {
                    float v = 0.5f*(a[el] + b[el]);
                    int e = g_bucket[base + el];       // broadcast load
                    g_blk[(size_t)e*IEDGE + tid] = v;  // coalesced
                    tr[el][xyt] = v;                   // stage transpose
                }
            }
        }
        __syncthreads();
        for (int el = 0; el < ne; el++) {
            int e = g_bucket[base + el];
            for (int j = tid; j < IEDGE; j += blockDim.x)
                g_blkT[(size_t)e*IEDGE + j] = tr[el][j];   // coalesced
        }
        __syncthreads();
    }
}

// ---------------- final single-pass write of M: zero strip, then ordered += of blocks ----------------
__global__ void __launch_bounds__(512) k_write(const int* __restrict__ ei, float* __restrict__ M) {
    int i   = blockIdx.x;
    int tid = threadIdx.x;   // 512
    float4* M4 = (float4*)M;
    size_t b4 = (size_t)i * STRIP4;
    float4 z = make_float4(0.f, 0.f, 0.f, 0.f);
    for (int j = tid; j < STRIP4; j += 512) M4[b4 + j] = z;
    __syncthreads();
    if (tid >= IEDGE) return;
    int x = tid/DD, y = tid - (tid/DD)*DD;
    size_t rowbase = (size_t)(i*DD + x)*NDIM + y;
    M[rowbase + (size_t)i*DD] += g_nblk[i*IEDGE + tid];   // diagonal node block
    int lo = g_rowoff[i], hi = g_rowoff[i+1];
    for (int q = lo; q < hi; q++) {
        int v = g_rentry[q];                 // broadcast
        int e = v >> 1, f = v & 1;
        int j = f ? ei[e] : ei[EE + e];      // column node of this block
        float val = f ? g_blkT[(size_t)e*IEDGE + tid] : g_blk[(size_t)e*IEDGE + tid];
        M[rowbase + (size_t)j*DD] += val;    // same thread owns (x,y) -> ordered, race-free
    }
}

// ---------------- launcher ----------------
extern "C" void kernel_launch(void* const* d_in, const int* in_sizes, int n_in,
                              void* d_out, int out_size) {
    const float* nf    = (const float*)d_in[0];
    const float* na    = (const float*)d_in[1];
    const float* ef    = (const float*)d_in[2];
    const float* ea    = (const float*)d_in[3];
    const int*   ei    = (const int*)d_in[4];
    const int*   ntype = (const int*)d_in[5];
    const int*   etype = (const int*)d_in[6];
    const float* Wmsg  = (const float*)d_in[7];
    const float* Wattr = (const float*)d_in[8];
    const float* Wem   = (const float*)d_in[9];
    const float* Wproj = (const float*)d_in[10];
    const float* Wnode = (const float*)d_in[11];
    const float* Wedge = (const float*)d_in[12];
    const float* cobn  = (const float*)d_in[13];
    const float* cobe  = (const float*)d_in[14];
    float* M = (float*)d_out;

    k_pre_node<<<(TT*FF*IEDGE + 255)/256, 256>>>(Wnode, cobn);
    k_pre_edge<<<(PP*KK*IEDGE + 255)/256, 256>>>(Wedge, cobe);
    k_node_prep<<<NN, FF>>>(nf, na, Wmsg, Wattr);
    k_hist<<<(EE + 255)/256, 256>>>(ei, etype);
    k_scan<<<1, 1024>>>();
    k_bucket<<<(EE + 255)/256, 256>>>(ei, etype);
    k_gather<<<NN, FF>>>(ei);
    k_node_out<<<NN, 160>>>(Wem, Wproj, ntype);
    k_edge_msg<<<1480, 128>>>(ef, ea, Wem, Wproj, ei);
    k_edge_blocks<<<dim3(64, PP), 192>>>();
    k_write<<<NN, 512>>>(ei, M);
}